// round 3
// baseline (speedup 1.0000x reference)
#include <cuda_runtime.h>
#include <cuda_bf16.h>
#include <cstdint>

// Problem constants (fixed-shape problem, from reference_code)
#define N_NODES 100000
#define D_FEAT  256
#define H1      128
#define H2      64
#define N_EDGES 1600000

// Scratch buffers (device globals: allocation-free scratch).
__device__ float g_xw0[(size_t)N_NODES * H1];   // X @ W0
__device__ float g_h1 [(size_t)N_NODES * H1];   // spmm1 accumulator
__device__ float g_hw1[(size_t)N_NODES * H2];   // relu(h1) @ W1
__device__ float g_h2 [(size_t)N_NODES * H2];   // spmm2 accumulator
__device__ int   g_is64;                        // edge index dtype flag

// ---------------------------------------------------------------------------
// dtype probe: are edge indices int64 or int32?
// Two packed int32s < 100000 always yield an int64 >= 2^32, so 64 in-range
// int64 reads <=> data really is int64.
// ---------------------------------------------------------------------------
__global__ void detect_dtype_kernel(const void* __restrict__ src) {
    if (threadIdx.x == 0 && blockIdx.x == 0) {
        const long long* p = (const long long*)src;
        int ok = 1;
        for (int i = 0; i < 64; i++) {
            long long v = p[i];
            if (v < 0 || v >= N_NODES) { ok = 0; break; }
        }
        g_is64 = ok;
    }
}

// ---------------------------------------------------------------------------
// zero both accumulators (float4 stores)
// ---------------------------------------------------------------------------
__global__ void zero_acc_kernel() {
    const int n1 = N_NODES * H1 / 4;
    const int n2 = N_NODES * H2 / 4;
    int i = blockIdx.x * blockDim.x + threadIdx.x;
    float4 z = make_float4(0.f, 0.f, 0.f, 0.f);
    if (i < n1) ((float4*)g_h1)[i] = z;
    if (i < n2) ((float4*)g_h2)[i] = z;
}

// ---------------------------------------------------------------------------
// Register-tiled fp32 GEMM body: C[M,N] = op(A)[M,K] @ B[K,N]
// ---------------------------------------------------------------------------
template<int BM, int BN, int BK, int TM, int TN, bool RELU_A>
__device__ __forceinline__ void gemm_body(const float* __restrict__ A,
                                          const float* __restrict__ B,
                                          float* __restrict__ C,
                                          int M, int K, int N)
{
    __shared__ float As[BK][BM];   // transposed A tile
    __shared__ float Bs[BK][BN];

    constexpr int THREADS = (BM / TM) * (BN / TN);   // 256
    const int tid = threadIdx.x;
    const int bm  = blockIdx.x * BM;
    const int tx  = tid % (BN / TN);
    const int ty  = tid / (BN / TN);

    float acc[TM][TN];
#pragma unroll
    for (int i = 0; i < TM; i++)
#pragma unroll
        for (int j = 0; j < TN; j++) acc[i][j] = 0.f;

    for (int k0 = 0; k0 < K; k0 += BK) {
        constexpr int A_ELEMS = BM * BK;
#pragma unroll
        for (int off = 0; off < A_ELEMS; off += THREADS * 4) {
            int idx = off + tid * 4;
            if (idx < A_ELEMS) {
                int ar  = idx / BK;
                int ac  = idx % BK;
                int grow = bm + ar;
                float4 v = make_float4(0.f, 0.f, 0.f, 0.f);
                if (grow < M)
                    v = *(const float4*)(A + (size_t)grow * K + k0 + ac);
                if (RELU_A) {
                    v.x = fmaxf(v.x, 0.f); v.y = fmaxf(v.y, 0.f);
                    v.z = fmaxf(v.z, 0.f); v.w = fmaxf(v.w, 0.f);
                }
                As[ac + 0][ar] = v.x;
                As[ac + 1][ar] = v.y;
                As[ac + 2][ar] = v.z;
                As[ac + 3][ar] = v.w;
            }
        }
        constexpr int B_ELEMS = BK * BN;
#pragma unroll
        for (int off = 0; off < B_ELEMS; off += THREADS * 4) {
            int idx = off + tid * 4;
            if (idx < B_ELEMS) {
                int br = idx / BN;
                int bc = idx % BN;
                *(float4*)&Bs[br][bc] =
                    *(const float4*)(B + (size_t)(k0 + br) * N + bc);
            }
        }
        __syncthreads();

#pragma unroll
        for (int kk = 0; kk < BK; kk++) {
            float a[TM], b[TN];
#pragma unroll
            for (int i = 0; i < TM; i++) a[i] = As[kk][ty * TM + i];
#pragma unroll
            for (int j = 0; j < TN; j++) b[j] = Bs[kk][tx * TN + j];
#pragma unroll
            for (int i = 0; i < TM; i++)
#pragma unroll
                for (int j = 0; j < TN; j++)
                    acc[i][j] += a[i] * b[j];
        }
        __syncthreads();
    }

#pragma unroll
    for (int i = 0; i < TM; i++) {
        int row = bm + ty * TM + i;
        if (row < M) {
#pragma unroll
            for (int j = 0; j < TN; j += 4) {
                float4 v = make_float4(acc[i][j], acc[i][j + 1],
                                       acc[i][j + 2], acc[i][j + 3]);
                *(float4*)(C + (size_t)row * N + tx * TN + j) = v;
            }
        }
    }
}

__global__ void gemm1_kernel(const float* __restrict__ x,
                             const float* __restrict__ W0) {
    gemm_body<128, 128, 16, 8, 8, false>(x, W0, g_xw0, N_NODES, D_FEAT, H1);
}

__global__ void gemm2_kernel(const float* __restrict__ W1) {
    gemm_body<128, 64, 16, 8, 4, true>(g_h1, W1, g_hw1, N_NODES, H1, H2);
}

// ---------------------------------------------------------------------------
// SPMM scatter: out[dst] += w * h[src], F floats per row.
// Sub-warp of F/4 lanes per edge; float4 gather + red.global.add.v4.f32.
// Edge index dtype resolved at runtime via g_is64.
// ---------------------------------------------------------------------------
__device__ __forceinline__ void red_add_f4(float* addr, float4 v) {
    asm volatile("red.global.add.v4.f32 [%0], {%1, %2, %3, %4};"
                 :: "l"(addr), "f"(v.x), "f"(v.y), "f"(v.z), "f"(v.w)
                 : "memory");
}

__device__ __forceinline__ long long load_idx(const void* p, int e, int is64) {
    return is64 ? ((const long long*)p)[e] : (long long)((const int*)p)[e];
}

template<int F>
__device__ __forceinline__ void spmm_body(const void* __restrict__ src,
                                          const void* __restrict__ dst,
                                          const float* __restrict__ w,
                                          const float* __restrict__ h,
                                          float* __restrict__ out, int E)
{
    constexpr int LPE = F / 4;        // lanes per edge
    constexpr int EPW = 32 / LPE;     // edges per warp
    int warp = (int)(((long long)blockIdx.x * blockDim.x + threadIdx.x) >> 5);
    int lane = threadIdx.x & 31;
    int e    = warp * EPW + lane / LPE;
    int sl   = lane % LPE;
    if (e >= E) return;
    int is64 = g_is64;
    long long s = load_idx(src, e, is64);
    long long d = load_idx(dst, e, is64);
    // safety guard: never fault, even if dtype detection is somehow wrong
    if ((unsigned long long)s >= N_NODES || (unsigned long long)d >= N_NODES)
        return;
    float wt = w[e];
    float4 v = ((const float4*)(h + s * F))[sl];
    v.x *= wt; v.y *= wt; v.z *= wt; v.w *= wt;
    red_add_f4((float*)(((float4*)(out + d * F)) + sl), v);
}

__global__ void spmm1_kernel(const void* __restrict__ src,
                             const void* __restrict__ dst,
                             const float* __restrict__ w, int E) {
    spmm_body<H1>(src, dst, w, g_xw0, g_h1, E);
}

__global__ void spmm2_kernel(const void* __restrict__ src,
                             const void* __restrict__ dst,
                             const float* __restrict__ w, int E) {
    spmm_body<H2>(src, dst, w, g_hw1, g_h2, E);
}

// ---------------------------------------------------------------------------
// Fused relu + softmax over rows of 64, one warp per node
// ---------------------------------------------------------------------------
__global__ void relu_softmax_kernel(float* __restrict__ out, int n)
{
    int warp = (int)(((long long)blockIdx.x * blockDim.x + threadIdx.x) >> 5);
    int lane = threadIdx.x & 31;
    if (warp >= n) return;
    const float* row = g_h2 + (size_t)warp * 64;
    float v0 = fmaxf(row[lane], 0.f);
    float v1 = fmaxf(row[lane + 32], 0.f);
    float m = fmaxf(v0, v1);
#pragma unroll
    for (int o = 16; o; o >>= 1) m = fmaxf(m, __shfl_xor_sync(~0u, m, o));
    float e0 = __expf(v0 - m);
    float e1 = __expf(v1 - m);
    float s = e0 + e1;
#pragma unroll
    for (int o = 16; o; o >>= 1) s += __shfl_xor_sync(~0u, s, o);
    float inv = 1.f / s;
    float* orow = out + (size_t)warp * 64;
    orow[lane]      = e0 * inv;
    orow[lane + 32] = e1 * inv;
}

// ---------------------------------------------------------------------------
// Launch
// ---------------------------------------------------------------------------
extern "C" void kernel_launch(void* const* d_in, const int* in_sizes, int n_in,
                              void* d_out, int out_size)
{
    // Identify inputs by element count. The three edge arrays share a size
    // (1.6M, or 3.2M for src/dst if int64 is reported in 4-byte units).
    const float* x  = nullptr;
    const float* W0 = nullptr;
    const float* W1 = nullptr;
    const void*  edge_buf[3] = {nullptr, nullptr, nullptr};
    int          edge_sz [3] = {0, 0, 0};
    int n_edge_bufs = 0;

    for (int i = 0; i < n_in; i++) {
        int sz = in_sizes[i];
        if (sz == N_NODES * D_FEAT)       x  = (const float*)d_in[i];
        else if (sz == D_FEAT * H1)       W0 = (const float*)d_in[i];
        else if (sz == H1 * H2)           W1 = (const float*)d_in[i];
        else if (n_edge_bufs < 3) {
            edge_buf[n_edge_bufs] = d_in[i];
            edge_sz [n_edge_bufs] = sz;
            n_edge_bufs++;
        }
    }
    // Default: dict order (src, dst, weight). If exactly one edge buffer is
    // smaller than the others, that one is the fp32 weight array.
    const void* esrc = edge_buf[0];
    const void* edst = edge_buf[1];
    const float* ew  = (const float*)edge_buf[2];
    if (edge_sz[0] != edge_sz[1] || edge_sz[1] != edge_sz[2]) {
        // find min-size buffer -> weights; remaining two keep order (src, dst)
        int wi = 0;
        if (edge_sz[1] < edge_sz[wi]) wi = 1;
        if (edge_sz[2] < edge_sz[wi]) wi = 2;
        const void* rest[2]; int r = 0;
        for (int i = 0; i < 3; i++) if (i != wi) rest[r++] = edge_buf[i];
        esrc = rest[0]; edst = rest[1];
        ew   = (const float*)edge_buf[wi];
    }
    float* out = (float*)d_out;
    const int E = N_EDGES;   // fixed-shape problem

    // probe edge index dtype (int64 vs harness-narrowed int32)
    detect_dtype_kernel<<<1, 32>>>(esrc);

    // zero scatter accumulators
    {
        int n4 = N_NODES * H1 / 4;
        zero_acc_kernel<<<(n4 + 255) / 256, 256>>>();
    }

    // layer 1 GEMM: xw0 = X @ W0
    gemm1_kernel<<<(N_NODES + 127) / 128, 256>>>(x, W0);

    // spmm1: h1[dst] += w * xw0[src]   (F=128 -> 1 edge per warp)
    {
        long long threads = (long long)E * 32;
        int blocks = (int)((threads + 255) / 256);
        spmm1_kernel<<<blocks, 256>>>(esrc, edst, ew, E);
    }

    // layer 2 GEMM: hw1 = relu(h1) @ W1
    gemm2_kernel<<<(N_NODES + 127) / 128, 256>>>(W1);

    // spmm2: h2[dst] += w * hw1[src]   (F=64 -> 2 edges per warp)
    {
        long long threads = ((long long)E + 1) / 2 * 32;
        int blocks = (int)((threads + 255) / 256);
        spmm2_kernel<<<blocks, 256>>>(esrc, edst, ew, E);
    }

    // final: out = softmax(relu(h2), axis=-1)
    {
        long long threads = (long long)N_NODES * 32;
        int blocks = (int)((threads + 255) / 256);
        relu_softmax_kernel<<<blocks, 256>>>(out, N_NODES);
    }
}

// round 4
// speedup vs baseline: 1.6603x; 1.6603x over previous
#include <cuda_runtime.h>
#include <cuda_bf16.h>
#include <cstdint>

// Problem constants (fixed-shape problem, from reference_code)
#define N_NODES 100000
#define D_FEAT  256
#define H1      128
#define H2      64
#define N_EDGES 1600000

#define SCAN_BLK 1024
#define N_SCAN_BLOCKS ((N_NODES + SCAN_BLK - 1) / SCAN_BLK)   // 98

// Scratch buffers (device globals: allocation-free scratch).
__device__ float g_xw0[(size_t)N_NODES * H1];   // X @ W0
__device__ float g_h1 [(size_t)N_NODES * H1];   // spmm1 result (pre-relu)
__device__ float g_hw1[(size_t)N_NODES * H2];   // relu(h1) @ W1
__device__ int   g_is64;                        // edge index dtype flag

// CSR (by dst) built fresh each launch
__device__ int   g_cnt [N_NODES];               // histogram, then cursor
__device__ int   g_ptr [N_NODES + 1];           // row pointers
__device__ int   g_bsum[N_SCAN_BLOCKS];         // scan block sums
__device__ int   g_boff[N_SCAN_BLOCKS];         // scan block offsets
__device__ int   g_col [N_EDGES];               // src per edge (int32)
__device__ float g_wgt [N_EDGES];               // weight per edge

// ---------------------------------------------------------------------------
// f32x2 packed math (sm_103a; ptxas never auto-fuses — PTX only)
// ---------------------------------------------------------------------------
__device__ __forceinline__ unsigned long long pack2(float x, float y) {
    unsigned long long r;
    asm("mov.b64 %0, {%1, %2};" : "=l"(r) : "f"(x), "f"(y));
    return r;
}
__device__ __forceinline__ void unpack2(unsigned long long v, float& x, float& y) {
    asm("mov.b64 {%0, %1}, %2;" : "=f"(x), "=f"(y) : "l"(v));
}
__device__ __forceinline__ void fma2(unsigned long long& d,
                                     unsigned long long a,
                                     unsigned long long b) {
    asm("fma.rn.f32x2 %0, %1, %2, %0;" : "+l"(d) : "l"(a), "l"(b));
}

// ---------------------------------------------------------------------------
// dtype probe: int64 vs harness-narrowed int32 edge indices
// ---------------------------------------------------------------------------
__global__ void detect_dtype_kernel(const void* __restrict__ src) {
    if (threadIdx.x == 0 && blockIdx.x == 0) {
        const long long* p = (const long long*)src;
        int ok = 1;
        for (int i = 0; i < 64; i++) {
            long long v = p[i];
            if (v < 0 || v >= N_NODES) { ok = 0; break; }
        }
        g_is64 = ok;
    }
}

__device__ __forceinline__ int load_idx(const void* p, int e, int is64) {
    return is64 ? (int)((const long long*)p)[e] : ((const int*)p)[e];
}

// ---------------------------------------------------------------------------
// CSR build: zero -> histogram -> scan(3) -> scatter
// ---------------------------------------------------------------------------
__global__ void zero_cnt_kernel() {
    int i = blockIdx.x * blockDim.x + threadIdx.x;
    if (i < N_NODES) g_cnt[i] = 0;
}

__global__ void hist_kernel(const void* __restrict__ dst, int E) {
    int e = blockIdx.x * blockDim.x + threadIdx.x;
    if (e >= E) return;
    int d = load_idx(dst, e, g_is64);
    if ((unsigned)d < N_NODES) atomicAdd(&g_cnt[d], 1);
}

__global__ void scan1_kernel() {
    __shared__ int s[SCAN_BLK];
    int i = blockIdx.x * SCAN_BLK + threadIdx.x;
    int v = (i < N_NODES) ? g_cnt[i] : 0;
    s[threadIdx.x] = v;
    __syncthreads();
#pragma unroll
    for (int o = 1; o < SCAN_BLK; o <<= 1) {
        int t = (threadIdx.x >= o) ? s[threadIdx.x - o] : 0;
        __syncthreads();
        s[threadIdx.x] += t;
        __syncthreads();
    }
    int inc = s[threadIdx.x];
    if (i < N_NODES) g_ptr[i] = inc - v;              // block-exclusive
    if (threadIdx.x == SCAN_BLK - 1) g_bsum[blockIdx.x] = inc;
}

__global__ void scan2_kernel() {
    __shared__ int s[128];
    int tid = threadIdx.x;
    int v = (tid < N_SCAN_BLOCKS) ? g_bsum[tid] : 0;
    s[tid] = v;
    __syncthreads();
#pragma unroll
    for (int o = 1; o < 128; o <<= 1) {
        int t = (tid >= o) ? s[tid - o] : 0;
        __syncthreads();
        s[tid] += t;
        __syncthreads();
    }
    if (tid < N_SCAN_BLOCKS) g_boff[tid] = s[tid] - v; // exclusive
}

__global__ void scan3_kernel(int E) {
    int i = blockIdx.x * blockDim.x + threadIdx.x;
    if (i < N_NODES) {
        int p = g_ptr[i] + g_boff[i / SCAN_BLK];
        g_ptr[i] = p;
        g_cnt[i] = p;                                  // cursor for scatter
    }
    if (i == 0) g_ptr[N_NODES] = E;
}

__global__ void scatter_kernel(const void* __restrict__ src,
                               const void* __restrict__ dst,
                               const float* __restrict__ w, int E) {
    int e = blockIdx.x * blockDim.x + threadIdx.x;
    if (e >= E) return;
    int is64 = g_is64;
    int s = load_idx(src, e, is64);
    int d = load_idx(dst, e, is64);
    if ((unsigned)s >= N_NODES || (unsigned)d >= N_NODES) return;
    int pos = atomicAdd(&g_cnt[d], 1);
    g_col[pos] = s;
    g_wgt[pos] = w[e];
}

// ---------------------------------------------------------------------------
// Register-tiled fp32 GEMM with f32x2 inner product
// C[M,N] = op(A)[M,K] @ B[K,N]; RELU_A applies relu on A load.
// ---------------------------------------------------------------------------
template<int BM, int BN, int BK, int TM, int TN, bool RELU_A>
__device__ __forceinline__ void gemm_body(const float* __restrict__ A,
                                          const float* __restrict__ B,
                                          float* __restrict__ C,
                                          int M, int K, int N)
{
    __shared__ float As[BK][BM];   // transposed A tile
    __shared__ float Bs[BK][BN];

    constexpr int THREADS = (BM / TM) * (BN / TN);   // 256
    const int tid = threadIdx.x;
    const int bm  = blockIdx.x * BM;
    const int tx  = tid % (BN / TN);
    const int ty  = tid / (BN / TN);

    unsigned long long acc2[TM][TN / 2];
#pragma unroll
    for (int i = 0; i < TM; i++)
#pragma unroll
        for (int j = 0; j < TN / 2; j++) acc2[i][j] = 0ull;

    for (int k0 = 0; k0 < K; k0 += BK) {
        constexpr int A_ELEMS = BM * BK;
#pragma unroll
        for (int off = 0; off < A_ELEMS; off += THREADS * 4) {
            int idx = off + tid * 4;
            if (idx < A_ELEMS) {
                int ar  = idx / BK;
                int ac  = idx % BK;
                int grow = bm + ar;
                float4 v = make_float4(0.f, 0.f, 0.f, 0.f);
                if (grow < M)
                    v = *(const float4*)(A + (size_t)grow * K + k0 + ac);
                if (RELU_A) {
                    v.x = fmaxf(v.x, 0.f); v.y = fmaxf(v.y, 0.f);
                    v.z = fmaxf(v.z, 0.f); v.w = fmaxf(v.w, 0.f);
                }
                As[ac + 0][ar] = v.x;
                As[ac + 1][ar] = v.y;
                As[ac + 2][ar] = v.z;
                As[ac + 3][ar] = v.w;
            }
        }
        constexpr int B_ELEMS = BK * BN;
#pragma unroll
        for (int off = 0; off < B_ELEMS; off += THREADS * 4) {
            int idx = off + tid * 4;
            if (idx < B_ELEMS) {
                int br = idx / BN;
                int bc = idx % BN;
                *(float4*)&Bs[br][bc] =
                    *(const float4*)(B + (size_t)(k0 + br) * N + bc);
            }
        }
        __syncthreads();

#pragma unroll
        for (int kk = 0; kk < BK; kk++) {
            unsigned long long b2[TN / 2];
#pragma unroll
            for (int j = 0; j < TN / 2; j++)
                b2[j] = *(const unsigned long long*)&Bs[kk][tx * TN + 2 * j];
#pragma unroll
            for (int i = 0; i < TM; i++) {
                float a = As[kk][ty * TM + i];
                unsigned long long a2 = pack2(a, a);
#pragma unroll
                for (int j = 0; j < TN / 2; j++)
                    fma2(acc2[i][j], a2, b2[j]);
            }
        }
        __syncthreads();
    }

#pragma unroll
    for (int i = 0; i < TM; i++) {
        int row = bm + ty * TM + i;
        if (row < M) {
#pragma unroll
            for (int j = 0; j < TN; j += 4) {
                float4 v;
                unpack2(acc2[i][j / 2],     v.x, v.y);
                unpack2(acc2[i][j / 2 + 1], v.z, v.w);
                *(float4*)(C + (size_t)row * N + tx * TN + j) = v;
            }
        }
    }
}

__global__ void gemm1_kernel(const float* __restrict__ x,
                             const float* __restrict__ W0) {
    gemm_body<128, 128, 32, 8, 8, false>(x, W0, g_xw0, N_NODES, D_FEAT, H1);
}

__global__ void gemm2_kernel(const float* __restrict__ W1) {
    gemm_body<128, 64, 32, 8, 4, true>(g_h1, W1, g_hw1, N_NODES, H1, H2);
}

// ---------------------------------------------------------------------------
// CSR SPMM layer 1: h1[r] = sum_e w_e * xw0[col_e], F=128.
// One warp per row; lane holds float4 (cols lane*4 .. lane*4+3).
// ---------------------------------------------------------------------------
__global__ void spmm1_csr_kernel()
{
    int warp = (int)(((long long)blockIdx.x * blockDim.x + threadIdx.x) >> 5);
    int lane = threadIdx.x & 31;
    if (warp >= N_NODES) return;
    int p  = g_ptr[warp];
    int pe = g_ptr[warp + 1];
    const float4* __restrict__ h4 = (const float4*)g_xw0;
    float4 acc = make_float4(0.f, 0.f, 0.f, 0.f);

    for (; p + 4 <= pe; p += 4) {
        int   c0 = g_col[p],     c1 = g_col[p + 1];
        int   c2 = g_col[p + 2], c3 = g_col[p + 3];
        float w0 = g_wgt[p],     w1 = g_wgt[p + 1];
        float w2 = g_wgt[p + 2], w3 = g_wgt[p + 3];
        float4 v0 = h4[(size_t)c0 * 32 + lane];
        float4 v1 = h4[(size_t)c1 * 32 + lane];
        float4 v2 = h4[(size_t)c2 * 32 + lane];
        float4 v3 = h4[(size_t)c3 * 32 + lane];
        acc.x += w0 * v0.x + w1 * v1.x + w2 * v2.x + w3 * v3.x;
        acc.y += w0 * v0.y + w1 * v1.y + w2 * v2.y + w3 * v3.y;
        acc.z += w0 * v0.z + w1 * v1.z + w2 * v2.z + w3 * v3.z;
        acc.w += w0 * v0.w + w1 * v1.w + w2 * v2.w + w3 * v3.w;
    }
    for (; p < pe; p++) {
        int   c = g_col[p];
        float w = g_wgt[p];
        float4 v = h4[(size_t)c * 32 + lane];
        acc.x += w * v.x; acc.y += w * v.y;
        acc.z += w * v.z; acc.w += w * v.w;
    }
    ((float4*)g_h1)[(size_t)warp * 32 + lane] = acc;
}

// ---------------------------------------------------------------------------
// CSR SPMM layer 2 fused with relu + softmax, F=64.
// One warp per row; lane holds float2 (cols lane*2, lane*2+1).
// ---------------------------------------------------------------------------
__global__ void spmm2_softmax_kernel(float* __restrict__ out)
{
    int warp = (int)(((long long)blockIdx.x * blockDim.x + threadIdx.x) >> 5);
    int lane = threadIdx.x & 31;
    if (warp >= N_NODES) return;
    int p  = g_ptr[warp];
    int pe = g_ptr[warp + 1];
    const float2* __restrict__ h2p = (const float2*)g_hw1;
    float2 acc = make_float2(0.f, 0.f);

    for (; p + 4 <= pe; p += 4) {
        int   c0 = g_col[p],     c1 = g_col[p + 1];
        int   c2 = g_col[p + 2], c3 = g_col[p + 3];
        float w0 = g_wgt[p],     w1 = g_wgt[p + 1];
        float w2 = g_wgt[p + 2], w3 = g_wgt[p + 3];
        float2 v0 = h2p[(size_t)c0 * 32 + lane];
        float2 v1 = h2p[(size_t)c1 * 32 + lane];
        float2 v2 = h2p[(size_t)c2 * 32 + lane];
        float2 v3 = h2p[(size_t)c3 * 32 + lane];
        acc.x += w0 * v0.x + w1 * v1.x + w2 * v2.x + w3 * v3.x;
        acc.y += w0 * v0.y + w1 * v1.y + w2 * v2.y + w3 * v3.y;
    }
    for (; p < pe; p++) {
        int   c = g_col[p];
        float w = g_wgt[p];
        float2 v = h2p[(size_t)c * 32 + lane];
        acc.x += w * v.x; acc.y += w * v.y;
    }

    // relu + softmax over the 64 values held by the warp
    float v0 = fmaxf(acc.x, 0.f);
    float v1 = fmaxf(acc.y, 0.f);
    float m = fmaxf(v0, v1);
#pragma unroll
    for (int o = 16; o; o >>= 1) m = fmaxf(m, __shfl_xor_sync(~0u, m, o));
    float e0 = __expf(v0 - m);
    float e1 = __expf(v1 - m);
    float s = e0 + e1;
#pragma unroll
    for (int o = 16; o; o >>= 1) s += __shfl_xor_sync(~0u, s, o);
    float inv = 1.f / s;
    ((float2*)out)[(size_t)warp * 32 + lane] = make_float2(e0 * inv, e1 * inv);
}

// ---------------------------------------------------------------------------
// Launch
// ---------------------------------------------------------------------------
extern "C" void kernel_launch(void* const* d_in, const int* in_sizes, int n_in,
                              void* d_out, int out_size)
{
    // Identify inputs by element count (same logic that passed in R3).
    const float* x  = nullptr;
    const float* W0 = nullptr;
    const float* W1 = nullptr;
    const void*  edge_buf[3] = {nullptr, nullptr, nullptr};
    int          edge_sz [3] = {0, 0, 0};
    int n_edge_bufs = 0;

    for (int i = 0; i < n_in; i++) {
        int sz = in_sizes[i];
        if (sz == N_NODES * D_FEAT)       x  = (const float*)d_in[i];
        else if (sz == D_FEAT * H1)       W0 = (const float*)d_in[i];
        else if (sz == H1 * H2)           W1 = (const float*)d_in[i];
        else if (n_edge_bufs < 3) {
            edge_buf[n_edge_bufs] = d_in[i];
            edge_sz [n_edge_bufs] = sz;
            n_edge_bufs++;
        }
    }
    const void*  esrc = edge_buf[0];
    const void*  edst = edge_buf[1];
    const float* ew   = (const float*)edge_buf[2];
    if (edge_sz[0] != edge_sz[1] || edge_sz[1] != edge_sz[2]) {
        int wi = 0;
        if (edge_sz[1] < edge_sz[wi]) wi = 1;
        if (edge_sz[2] < edge_sz[wi]) wi = 2;
        const void* rest[2]; int r = 0;
        for (int i = 0; i < 3; i++) if (i != wi) rest[r++] = edge_buf[i];
        esrc = rest[0]; edst = rest[1];
        ew   = (const float*)edge_buf[wi];
    }
    float* out = (float*)d_out;
    const int E = N_EDGES;

    const int EBLK = (E + 255) / 256;
    const int NBLK = (N_NODES + 255) / 256;
    const int WBLK = (int)(((long long)N_NODES * 32 + 255) / 256);

    // dtype probe + CSR build
    detect_dtype_kernel<<<1, 32>>>(esrc);
    zero_cnt_kernel<<<NBLK, 256>>>();
    hist_kernel<<<EBLK, 256>>>(edst, E);
    scan1_kernel<<<N_SCAN_BLOCKS, SCAN_BLK>>>();
    scan2_kernel<<<1, 128>>>();
    scan3_kernel<<<NBLK, 256>>>(E);
    scatter_kernel<<<EBLK, 256>>>(esrc, edst, ew, E);

    // layer 1: xw0 = X @ W0, then h1 = A @ xw0 (CSR gather)
    gemm1_kernel<<<(N_NODES + 127) / 128, 256>>>(x, W0);
    spmm1_csr_kernel<<<WBLK, 256>>>();

    // layer 2: hw1 = relu(h1) @ W1, then out = softmax(relu(A @ hw1))
    gemm2_kernel<<<(N_NODES + 127) / 128, 256>>>(W1);
    spmm2_softmax_kernel<<<WBLK, 256>>>(out);
}

// round 6
// speedup vs baseline: 1.7432x; 1.0499x over previous
#include <cuda_runtime.h>
#include <cuda_bf16.h>
#include <cuda_fp16.h>
#include <cstdint>

// Problem constants (fixed-shape problem, from reference_code)
#define N_NODES 100000
#define D_FEAT  256
#define H1      128
#define H2      64
#define N_EDGES 1600000

#define SCAN_BLK 1024
#define N_SCAN_BLOCKS ((N_NODES + SCAN_BLK - 1) / SCAN_BLK)   // 98

// Scratch buffers (device globals: allocation-free scratch).
__device__ __half g_xw0h[(size_t)N_NODES * H1];  // X @ W0, fp16 (gather operand)
__device__ float  g_h1 [(size_t)N_NODES * H1];   // spmm1 result fp32 (pre-relu)
__device__ __half g_hw1h[(size_t)N_NODES * H2];  // relu(h1) @ W1, fp16 (gather operand)
__device__ int    g_is64;                        // edge index dtype flag

// CSR (by dst) built fresh each launch; col+weight packed in one int2
__device__ int   g_cnt [N_NODES];                // histogram, then cursor
__device__ int   g_ptr [N_NODES + 1];            // row pointers
__device__ int   g_bsum[N_SCAN_BLOCKS];
__device__ int   g_boff[N_SCAN_BLOCKS];
__device__ int2  g_edge[N_EDGES];                // {col, __float_as_int(w)}

// ---------------------------------------------------------------------------
// f32x2 packed math (sm_103a; PTX-only — ptxas never auto-fuses)
// ---------------------------------------------------------------------------
__device__ __forceinline__ unsigned long long pack2(float x, float y) {
    unsigned long long r;
    asm("mov.b64 %0, {%1, %2};" : "=l"(r) : "f"(x), "f"(y));
    return r;
}
__device__ __forceinline__ void unpack2(unsigned long long v, float& x, float& y) {
    asm("mov.b64 {%0, %1}, %2;" : "=f"(x), "=f"(y) : "l"(v));
}
__device__ __forceinline__ void fma2(unsigned long long& d,
                                     unsigned long long a,
                                     unsigned long long b) {
    asm("fma.rn.f32x2 %0, %1, %2, %0;" : "+l"(d) : "l"(a), "l"(b));
}

// ---------------------------------------------------------------------------
// dtype probe (block 0, thread 0) + zero histogram (whole grid)
// ---------------------------------------------------------------------------
__global__ void detect_zero_kernel(const void* __restrict__ src) {
    int i = blockIdx.x * blockDim.x + threadIdx.x;
    if (i < N_NODES) g_cnt[i] = 0;
    if (i == 0) {
        const long long* p = (const long long*)src;
        int ok = 1;
        for (int k = 0; k < 64; k++) {
            long long v = p[k];
            if (v < 0 || v >= N_NODES) { ok = 0; break; }
        }
        g_is64 = ok;
    }
}

__device__ __forceinline__ int load_idx(const void* p, int e, int is64) {
    return is64 ? (int)((const long long*)p)[e] : ((const int*)p)[e];
}

// ---------------------------------------------------------------------------
// CSR build: histogram -> scan(3) -> scatter
// ---------------------------------------------------------------------------
__global__ void hist_kernel(const void* __restrict__ dst, int E) {
    int e = blockIdx.x * blockDim.x + threadIdx.x;
    if (e >= E) return;
    int d = load_idx(dst, e, g_is64);
    if ((unsigned)d < N_NODES) atomicAdd(&g_cnt[d], 1);
}

__global__ void scan1_kernel() {
    __shared__ int s[SCAN_BLK];
    int i = blockIdx.x * SCAN_BLK + threadIdx.x;
    int v = (i < N_NODES) ? g_cnt[i] : 0;
    s[threadIdx.x] = v;
    __syncthreads();
#pragma unroll
    for (int o = 1; o < SCAN_BLK; o <<= 1) {
        int t = (threadIdx.x >= o) ? s[threadIdx.x - o] : 0;
        __syncthreads();
        s[threadIdx.x] += t;
        __syncthreads();
    }
    int inc = s[threadIdx.x];
    if (i < N_NODES) g_ptr[i] = inc - v;
    if (threadIdx.x == SCAN_BLK - 1) g_bsum[blockIdx.x] = inc;
}

__global__ void scan2_kernel() {
    __shared__ int s[128];
    int tid = threadIdx.x;
    int v = (tid < N_SCAN_BLOCKS) ? g_bsum[tid] : 0;
    s[tid] = v;
    __syncthreads();
#pragma unroll
    for (int o = 1; o < 128; o <<= 1) {
        int t = (tid >= o) ? s[tid - o] : 0;
        __syncthreads();
        s[tid] += t;
        __syncthreads();
    }
    if (tid < N_SCAN_BLOCKS) g_boff[tid] = s[tid] - v;
}

__global__ void scan3_kernel(int E) {
    int i = blockIdx.x * blockDim.x + threadIdx.x;
    if (i < N_NODES) {
        int p = g_ptr[i] + g_boff[i / SCAN_BLK];
        g_ptr[i] = p;
        g_cnt[i] = p;
    }
    if (i == 0) g_ptr[N_NODES] = E;
}

__global__ void scatter_kernel(const void* __restrict__ src,
                               const void* __restrict__ dst,
                               const float* __restrict__ w, int E) {
    int e = blockIdx.x * blockDim.x + threadIdx.x;
    if (e >= E) return;
    int is64 = g_is64;
    int s = load_idx(src, e, is64);
    int d = load_idx(dst, e, is64);
    if ((unsigned)s >= N_NODES || (unsigned)d >= N_NODES) return;
    int pos = atomicAdd(&g_cnt[d], 1);
    g_edge[pos] = make_int2(s, __float_as_int(w[e]));
}

// ---------------------------------------------------------------------------
// Register-tiled fp32 GEMM with f32x2 inner product, fp16 output.
// C_half[M,N] = op(A)[M,K] @ B[K,N]; RELU_A applies relu on A load.
// ---------------------------------------------------------------------------
template<int BM, int BN, int BK, int TM, int TN, bool RELU_A>
__device__ __forceinline__ void gemm_body_h(const float* __restrict__ A,
                                            const float* __restrict__ B,
                                            __half* __restrict__ C,
                                            int M, int K, int N)
{
    __shared__ float As[BK][BM];   // transposed A tile
    __shared__ float Bs[BK][BN];

    constexpr int THREADS = (BM / TM) * (BN / TN);   // 256
    const int tid = threadIdx.x;
    const int bm  = blockIdx.x * BM;
    const int tx  = tid % (BN / TN);
    const int ty  = tid / (BN / TN);

    unsigned long long acc2[TM][TN / 2];
#pragma unroll
    for (int i = 0; i < TM; i++)
#pragma unroll
        for (int j = 0; j < TN / 2; j++) acc2[i][j] = 0ull;

    for (int k0 = 0; k0 < K; k0 += BK) {
        constexpr int A_ELEMS = BM * BK;
#pragma unroll
        for (int off = 0; off < A_ELEMS; off += THREADS * 4) {
            int idx = off + tid * 4;
            if (idx < A_ELEMS) {
                int ar  = idx / BK;
                int ac  = idx % BK;
                int grow = bm + ar;
                float4 v = make_float4(0.f, 0.f, 0.f, 0.f);
                if (grow < M)
                    v = *(const float4*)(A + (size_t)grow * K + k0 + ac);
                if (RELU_A) {
                    v.x = fmaxf(v.x, 0.f); v.y = fmaxf(v.y, 0.f);
                    v.z = fmaxf(v.z, 0.f); v.w = fmaxf(v.w, 0.f);
                }
                As[ac + 0][ar] = v.x;
                As[ac + 1][ar] = v.y;
                As[ac + 2][ar] = v.z;
                As[ac + 3][ar] = v.w;
            }
        }
        constexpr int B_ELEMS = BK * BN;
#pragma unroll
        for (int off = 0; off < B_ELEMS; off += THREADS * 4) {
            int idx = off + tid * 4;
            if (idx < B_ELEMS) {
                int br = idx / BN;
                int bc = idx % BN;
                *(float4*)&Bs[br][bc] =
                    *(const float4*)(B + (size_t)(k0 + br) * N + bc);
            }
        }
        __syncthreads();

#pragma unroll
        for (int kk = 0; kk < BK; kk++) {
            unsigned long long b2[TN / 2];
#pragma unroll
            for (int j = 0; j < TN / 2; j++)
                b2[j] = *(const unsigned long long*)&Bs[kk][tx * TN + 2 * j];
#pragma unroll
            for (int i = 0; i < TM; i++) {
                float a = As[kk][ty * TM + i];
                unsigned long long a2 = pack2(a, a);
#pragma unroll
                for (int j = 0; j < TN / 2; j++)
                    fma2(acc2[i][j], a2, b2[j]);
            }
        }
        __syncthreads();
    }

    // epilogue: convert to half2, vector stores
#pragma unroll
    for (int i = 0; i < TM; i++) {
        int row = bm + ty * TM + i;
        if (row < M) {
            __half2 h[TN / 2];
#pragma unroll
            for (int j = 0; j < TN / 2; j++) {
                float lo, hi;
                unpack2(acc2[i][j], lo, hi);
                h[j] = __floats2half2_rn(lo, hi);
            }
#pragma unroll
            for (int j = 0; j < TN / 2; j += 2)
                *(uint2*)(C + (size_t)row * N + tx * TN + 2 * j) =
                    *(uint2*)&h[j];
        }
    }
}

// GEMM2 needs fp32 A (g_h1) but also stores fp16; identical body works since
// templated on pointers. GEMM1: A=x fp32 input.
__global__ void gemm1_kernel(const float* __restrict__ x,
                             const float* __restrict__ W0) {
    gemm_body_h<128, 128, 32, 8, 8, false>(x, W0, g_xw0h, N_NODES, D_FEAT, H1);
}

__global__ void gemm2_kernel(const float* __restrict__ W1) {
    gemm_body_h<128, 64, 32, 8, 4, true>(g_h1, W1, g_hw1h, N_NODES, H1, H2);
}

// ---------------------------------------------------------------------------
// CSR SPMM layer 1: h1[r] = sum_e w_e * xw0[col_e], F=128 halves.
// One warp per row; lane loads uint2 = 4 halves (cols lane*4..lane*4+3).
// ---------------------------------------------------------------------------
__global__ void spmm1_csr_kernel()
{
    int warp = (int)(((long long)blockIdx.x * blockDim.x + threadIdx.x) >> 5);
    int lane = threadIdx.x & 31;
    if (warp >= N_NODES) return;
    int p  = g_ptr[warp];
    int pe = g_ptr[warp + 1];
    const uint2* __restrict__ h4 = (const uint2*)g_xw0h;   // 4 halves / elem
    float4 acc = make_float4(0.f, 0.f, 0.f, 0.f);

    for (; p + 4 <= pe; p += 4) {
        int2 e0 = g_edge[p],     e1 = g_edge[p + 1];
        int2 e2 = g_edge[p + 2], e3 = g_edge[p + 3];
        uint2 r0 = h4[(size_t)e0.x * 32 + lane];
        uint2 r1 = h4[(size_t)e1.x * 32 + lane];
        uint2 r2 = h4[(size_t)e2.x * 32 + lane];
        uint2 r3 = h4[(size_t)e3.x * 32 + lane];
        float w0 = __int_as_float(e0.y), w1 = __int_as_float(e1.y);
        float w2 = __int_as_float(e2.y), w3 = __int_as_float(e3.y);
        float2 a0 = __half22float2(*(__half2*)&r0.x);
        float2 b0 = __half22float2(*(__half2*)&r0.y);
        float2 a1 = __half22float2(*(__half2*)&r1.x);
        float2 b1 = __half22float2(*(__half2*)&r1.y);
        float2 a2 = __half22float2(*(__half2*)&r2.x);
        float2 b2 = __half22float2(*(__half2*)&r2.y);
        float2 a3 = __half22float2(*(__half2*)&r3.x);
        float2 b3 = __half22float2(*(__half2*)&r3.y);
        acc.x += w0 * a0.x + w1 * a1.x + w2 * a2.x + w3 * a3.x;
        acc.y += w0 * a0.y + w1 * a1.y + w2 * a2.y + w3 * a3.y;
        acc.z += w0 * b0.x + w1 * b1.x + w2 * b2.x + w3 * b3.x;
        acc.w += w0 * b0.y + w1 * b1.y + w2 * b2.y + w3 * b3.y;
    }
    for (; p < pe; p++) {
        int2 e = g_edge[p];
        float w = __int_as_float(e.y);
        uint2 r = h4[(size_t)e.x * 32 + lane];
        float2 a = __half22float2(*(__half2*)&r.x);
        float2 b = __half22float2(*(__half2*)&r.y);
        acc.x += w * a.x; acc.y += w * a.y;
        acc.z += w * b.x; acc.w += w * b.y;
    }
    ((float4*)g_h1)[(size_t)warp * 32 + lane] = acc;
}

// ---------------------------------------------------------------------------
// CSR SPMM layer 2 fused with relu + softmax, F=64 halves.
// One warp per row; lane loads uint = 2 halves (cols lane*2, lane*2+1).
// ---------------------------------------------------------------------------
__global__ void spmm2_softmax_kernel(float* __restrict__ out)
{
    int warp = (int)(((long long)blockIdx.x * blockDim.x + threadIdx.x) >> 5);
    int lane = threadIdx.x & 31;
    if (warp >= N_NODES) return;
    int p  = g_ptr[warp];
    int pe = g_ptr[warp + 1];
    const unsigned* __restrict__ h2p = (const unsigned*)g_hw1h;  // 2 halves
    float2 acc = make_float2(0.f, 0.f);

    for (; p + 4 <= pe; p += 4) {
        int2 e0 = g_edge[p],     e1 = g_edge[p + 1];
        int2 e2 = g_edge[p + 2], e3 = g_edge[p + 3];
        unsigned r0 = h2p[(size_t)e0.x * 32 + lane];
        unsigned r1 = h2p[(size_t)e1.x * 32 + lane];
        unsigned r2 = h2p[(size_t)e2.x * 32 + lane];
        unsigned r3 = h2p[(size_t)e3.x * 32 + lane];
        float w0 = __int_as_float(e0.y), w1 = __int_as_float(e1.y);
        float w2 = __int_as_float(e2.y), w3 = __int_as_float(e3.y);
        float2 v0 = __half22float2(*(__half2*)&r0);
        float2 v1 = __half22float2(*(__half2*)&r1);
        float2 v2 = __half22float2(*(__half2*)&r2);
        float2 v3 = __half22float2(*(__half2*)&r3);
        acc.x += w0 * v0.x + w1 * v1.x + w2 * v2.x + w3 * v3.x;
        acc.y += w0 * v0.y + w1 * v1.y + w2 * v2.y + w3 * v3.y;
    }
    for (; p < pe; p++) {
        int2 e = g_edge[p];
        float w = __int_as_float(e.y);
        unsigned r = h2p[(size_t)e.x * 32 + lane];
        float2 v = __half22float2(*(__half2*)&r);
        acc.x += w * v.x; acc.y += w * v.y;
    }

    // relu + softmax over the 64 values held by the warp
    float v0 = fmaxf(acc.x, 0.f);
    float v1 = fmaxf(acc.y, 0.f);
    float m = fmaxf(v0, v1);
#pragma unroll
    for (int o = 16; o; o >>= 1) m = fmaxf(m, __shfl_xor_sync(~0u, m, o));
    float e0 = __expf(v0 - m);
    float e1 = __expf(v1 - m);
    float s = e0 + e1;
#pragma unroll
    for (int o = 16; o; o >>= 1) s += __shfl_xor_sync(~0u, s, o);
    float inv = 1.f / s;
    ((float2*)out)[(size_t)warp * 32 + lane] = make_float2(e0 * inv, e1 * inv);
}

// ---------------------------------------------------------------------------
// Launch
// ---------------------------------------------------------------------------
extern "C" void kernel_launch(void* const* d_in, const int* in_sizes, int n_in,
                              void* d_out, int out_size)
{
    // Identify inputs by element count (same logic that passed in R3/R4).
    const float* x  = nullptr;
    const float* W0 = nullptr;
    const float* W1 = nullptr;
    const void*  edge_buf[3] = {nullptr, nullptr, nullptr};
    int          edge_sz [3] = {0, 0, 0};
    int n_edge_bufs = 0;

    for (int i = 0; i < n_in; i++) {
        int sz = in_sizes[i];
        if (sz == N_NODES * D_FEAT)       x  = (const float*)d_in[i];
        else if (sz == D_FEAT * H1)       W0 = (const float*)d_in[i];
        else if (sz == H1 * H2)           W1 = (const float*)d_in[i];
        else if (n_edge_bufs < 3) {
            edge_buf[n_edge_bufs] = d_in[i];
            edge_sz [n_edge_bufs] = sz;
            n_edge_bufs++;
        }
    }
    const void*  esrc = edge_buf[0];
    const void*  edst = edge_buf[1];
    const float* ew   = (const float*)edge_buf[2];
    if (edge_sz[0] != edge_sz[1] || edge_sz[1] != edge_sz[2]) {
        int wi = 0;
        if (edge_sz[1] < edge_sz[wi]) wi = 1;
        if (edge_sz[2] < edge_sz[wi]) wi = 2;
        const void* rest[2]; int r = 0;
        for (int i = 0; i < 3; i++) if (i != wi) rest[r++] = edge_buf[i];
        esrc = rest[0]; edst = rest[1];
        ew   = (const float*)edge_buf[wi];
    }
    float* out = (float*)d_out;
    const int E = N_EDGES;

    const int EBLK = (E + 255) / 256;
    const int NBLK = (N_NODES + 255) / 256;
    const int WBLK = (int)(((long long)N_NODES * 32 + 255) / 256);

    // dtype probe + zero + CSR build
    detect_zero_kernel<<<NBLK, 256>>>(esrc);
    hist_kernel<<<EBLK, 256>>>(edst, E);
    scan1_kernel<<<N_SCAN_BLOCKS, SCAN_BLK>>>();
    scan2_kernel<<<1, 128>>>();
    scan3_kernel<<<NBLK, 256>>>(E);
    scatter_kernel<<<EBLK, 256>>>(esrc, edst, ew, E);

    // layer 1: xw0h = fp16(X @ W0), then h1 = A @ xw0 (CSR gather, fp32 acc)
    gemm1_kernel<<<(N_NODES + 127) / 128, 256>>>(x, W0);
    spmm1_csr_kernel<<<WBLK, 256>>>();

    // layer 2: hw1h = fp16(relu(h1) @ W1), then out = softmax(relu(A @ hw1))
    gemm2_kernel<<<(N_NODES + 127) / 128, 256>>>(W1);
    spmm2_softmax_kernel<<<WBLK, 256>>>(out);
}

// round 7
// speedup vs baseline: 2.7371x; 1.5702x over previous
#include <cuda_runtime.h>
#include <cuda_bf16.h>
#include <cuda_fp16.h>
#include <mma.h>
#include <cstdint>

using namespace nvcuda;

// Problem constants (fixed-shape problem, from reference_code)
#define N_NODES 100000
#define D_FEAT  256
#define H1      128
#define H2      64
#define N_EDGES 1600000

#define SCAN_BLK 1024
#define N_SCAN_BLOCKS ((N_NODES + SCAN_BLK - 1) / SCAN_BLK)   // 98

// Scratch buffers (device globals: allocation-free scratch).
__device__ __half g_xw0h[(size_t)N_NODES * H1];  // X @ W0, fp16 (gather operand)
__device__ float  g_h1 [(size_t)N_NODES * H1];   // spmm1 result fp32 (pre-relu)
__device__ __half g_hw1h[(size_t)N_NODES * H2];  // relu(h1) @ W1, fp16 (gather operand)
__device__ int    g_is64;                        // edge index dtype flag

// CSR (by dst) built fresh each launch; col+weight packed in one int2
__device__ int   g_cnt [N_NODES];                // histogram, then cursor
__device__ int   g_ptr [N_NODES + 1];            // row pointers
__device__ int   g_bsum[N_SCAN_BLOCKS];
__device__ int   g_boff[N_SCAN_BLOCKS];
__device__ int2  g_edge[N_EDGES];                // {col, __float_as_int(w)}

// ---------------------------------------------------------------------------
// f32x2 packed math (sm_103a; PTX-only — ptxas never auto-fuses)
// ---------------------------------------------------------------------------
__device__ __forceinline__ unsigned long long pack2(float x, float y) {
    unsigned long long r;
    asm("mov.b64 %0, {%1, %2};" : "=l"(r) : "f"(x), "f"(y));
    return r;
}
__device__ __forceinline__ void unpack2(unsigned long long v, float& x, float& y) {
    asm("mov.b64 {%0, %1}, %2;" : "=f"(x), "=f"(y) : "l"(v));
}
__device__ __forceinline__ void fma2(unsigned long long& d,
                                     unsigned long long a,
                                     unsigned long long b) {
    asm("fma.rn.f32x2 %0, %1, %2, %0;" : "+l"(d) : "l"(a), "l"(b));
}

// ---------------------------------------------------------------------------
// dtype probe (thread 0) + zero histogram (whole grid)
// ---------------------------------------------------------------------------
__global__ void detect_zero_kernel(const void* __restrict__ src) {
    int i = blockIdx.x * blockDim.x + threadIdx.x;
    if (i < N_NODES) g_cnt[i] = 0;
    if (i == 0) {
        const long long* p = (const long long*)src;
        int ok = 1;
        for (int k = 0; k < 64; k++) {
            long long v = p[k];
            if (v < 0 || v >= N_NODES) { ok = 0; break; }
        }
        g_is64 = ok;
    }
}

__device__ __forceinline__ int load_idx(const void* p, int e, int is64) {
    return is64 ? (int)((const long long*)p)[e] : ((const int*)p)[e];
}

// ---------------------------------------------------------------------------
// CSR build: histogram -> scan(3) -> scatter
// ---------------------------------------------------------------------------
__global__ void hist_kernel(const void* __restrict__ dst, int E) {
    int e = blockIdx.x * blockDim.x + threadIdx.x;
    if (e >= E) return;
    int d = load_idx(dst, e, g_is64);
    if ((unsigned)d < N_NODES) atomicAdd(&g_cnt[d], 1);
}

__global__ void scan1_kernel() {
    __shared__ int s[SCAN_BLK];
    int i = blockIdx.x * SCAN_BLK + threadIdx.x;
    int v = (i < N_NODES) ? g_cnt[i] : 0;
    s[threadIdx.x] = v;
    __syncthreads();
#pragma unroll
    for (int o = 1; o < SCAN_BLK; o <<= 1) {
        int t = (threadIdx.x >= o) ? s[threadIdx.x - o] : 0;
        __syncthreads();
        s[threadIdx.x] += t;
        __syncthreads();
    }
    int inc = s[threadIdx.x];
    if (i < N_NODES) g_ptr[i] = inc - v;
    if (threadIdx.x == SCAN_BLK - 1) g_bsum[blockIdx.x] = inc;
}

__global__ void scan2_kernel() {
    __shared__ int s[128];
    int tid = threadIdx.x;
    int v = (tid < N_SCAN_BLOCKS) ? g_bsum[tid] : 0;
    s[tid] = v;
    __syncthreads();
#pragma unroll
    for (int o = 1; o < 128; o <<= 1) {
        int t = (tid >= o) ? s[tid - o] : 0;
        __syncthreads();
        s[tid] += t;
        __syncthreads();
    }
    if (tid < N_SCAN_BLOCKS) g_boff[tid] = s[tid] - v;
}

__global__ void scan3_kernel(int E) {
    int i = blockIdx.x * blockDim.x + threadIdx.x;
    if (i < N_NODES) {
        int p = g_ptr[i] + g_boff[i / SCAN_BLK];
        g_ptr[i] = p;
        g_cnt[i] = p;
    }
    if (i == 0) g_ptr[N_NODES] = E;
}

__global__ void scatter_kernel(const void* __restrict__ src,
                               const void* __restrict__ dst,
                               const float* __restrict__ w, int E) {
    int e = blockIdx.x * blockDim.x + threadIdx.x;
    if (e >= E) return;
    int is64 = g_is64;
    int s = load_idx(src, e, is64);
    int d = load_idx(dst, e, is64);
    if ((unsigned)s >= N_NODES || (unsigned)d >= N_NODES) return;
    int pos = atomicAdd(&g_cnt[d], 1);
    g_edge[pos] = make_int2(s, __float_as_int(w[e]));
}

// ---------------------------------------------------------------------------
// GEMM1: tensor-core (wmma fp16 in / fp32 accum), output fp16.
// xw0h[M,128] = fp16( X[M,256] @ W0[256,128] )
// Block: 256 thr = 8 warps (4 m-warps x 2 n-warps); warp tile 32x64.
// BM=128, BN=128, BK=32.
// ---------------------------------------------------------------------------
#define G1_LDA 40    // 32 + 8 halves
#define G1_LDB 136   // 128 + 8 halves
#define G1_LDC 72    // 64 + 8 floats (epilogue staging, per column-half)
#define G1_AB_BYTES (128 * G1_LDA * 2 + 32 * G1_LDB * 2)   // 10240 + 8704
#define G1_C_BYTES  (128 * G1_LDC * 4)                     // 36864

__global__ void gemm1_wmma_kernel(const float* __restrict__ X,
                                  const float* __restrict__ W0) {
    __shared__ __align__(16) char smem[G1_C_BYTES];        // 36 KB (union)
    half*  As = (half*)smem;                               // [128][40]
    half*  Bs = (half*)(smem + 128 * G1_LDA * 2);          // [32][136]
    float* Cs = (float*)smem;                              // [128][72]

    const int tid   = threadIdx.x;
    const int warp  = tid >> 5;
    const int warpM = warp >> 1;        // 0..3
    const int warpN = warp & 1;         // 0..1
    const int bm    = blockIdx.x * 128;

    wmma::fragment<wmma::accumulator, 16, 16, 16, float> c[2][4];
#pragma unroll
    for (int i = 0; i < 2; i++)
#pragma unroll
        for (int j = 0; j < 4; j++) wmma::fill_fragment(c[i][j], 0.f);

    for (int k0 = 0; k0 < D_FEAT; k0 += 32) {
        // As: 128x32 fp32 -> fp16 (1024 float4 chunks, 4/thread)
#pragma unroll
        for (int t = 0; t < 4; t++) {
            int chunk = tid + t * 256;
            int row = chunk >> 3;
            int c4  = chunk & 7;
            int grow = bm + row;
            float4 v = make_float4(0.f, 0.f, 0.f, 0.f);
            if (grow < N_NODES)
                v = *(const float4*)(X + (size_t)grow * D_FEAT + k0 + c4 * 4);
            __half2 h0 = __floats2half2_rn(v.x, v.y);
            __half2 h1 = __floats2half2_rn(v.z, v.w);
            uint2 pk;
            pk.x = *(unsigned*)&h0;
            pk.y = *(unsigned*)&h1;
            *(uint2*)(As + (size_t)row * G1_LDA + c4 * 4) = pk;
        }
        // Bs: 32x128 fp32 -> fp16 (1024 float4 chunks, 4/thread)
#pragma unroll
        for (int t = 0; t < 4; t++) {
            int chunk = tid + t * 256;
            int row = chunk >> 5;
            int c4  = chunk & 31;
            float4 v = *(const float4*)(W0 + (size_t)(k0 + row) * H1 + c4 * 4);
            __half2 h0 = __floats2half2_rn(v.x, v.y);
            __half2 h1 = __floats2half2_rn(v.z, v.w);
            uint2 pk;
            pk.x = *(unsigned*)&h0;
            pk.y = *(unsigned*)&h1;
            *(uint2*)(Bs + (size_t)row * G1_LDB + c4 * 4) = pk;
        }
        __syncthreads();

#pragma unroll
        for (int kk = 0; kk < 32; kk += 16) {
            wmma::fragment<wmma::matrix_a, 16, 16, 16, half, wmma::row_major> a[2];
            wmma::fragment<wmma::matrix_b, 16, 16, 16, half, wmma::row_major> b[4];
#pragma unroll
            for (int i = 0; i < 2; i++)
                wmma::load_matrix_sync(a[i],
                    As + (size_t)(warpM * 32 + i * 16) * G1_LDA + kk, G1_LDA);
#pragma unroll
            for (int j = 0; j < 4; j++)
                wmma::load_matrix_sync(b[j],
                    Bs + (size_t)kk * G1_LDB + warpN * 64 + j * 16, G1_LDB);
#pragma unroll
            for (int i = 0; i < 2; i++)
#pragma unroll
                for (int j = 0; j < 4; j++)
                    wmma::mma_sync(c[i][j], a[i], b[j], c[i][j]);
        }
        __syncthreads();
    }

    // Epilogue in two column-halves through smem staging (reuses As/Bs space)
#pragma unroll
    for (int p = 0; p < 2; p++) {
        if (warpN == p) {
#pragma unroll
            for (int i = 0; i < 2; i++)
#pragma unroll
                for (int j = 0; j < 4; j++)
                    wmma::store_matrix_sync(
                        Cs + (size_t)(warpM * 32 + i * 16) * G1_LDC + j * 16,
                        c[i][j], G1_LDC, wmma::mem_row_major);
        }
        __syncthreads();
        // write this 128x64 half to global fp16 (2048 4-elem chunks, 8/thread)
#pragma unroll
        for (int t = 0; t < 8; t++) {
            int chunk = tid + t * 256;
            int row = chunk >> 4;
            int c4  = chunk & 15;
            int grow = bm + row;
            if (grow < N_NODES) {
                const float* s = Cs + (size_t)row * G1_LDC + c4 * 4;
                __half2 h0 = __floats2half2_rn(s[0], s[1]);
                __half2 h1 = __floats2half2_rn(s[2], s[3]);
                uint2 pk;
                pk.x = *(unsigned*)&h0;
                pk.y = *(unsigned*)&h1;
                *(uint2*)(g_xw0h + (size_t)grow * H1 + p * 64 + c4 * 4) = pk;
            }
        }
        __syncthreads();
    }
}

// ---------------------------------------------------------------------------
// GEMM2 (f32x2 scalar path — keeps full fp32 input precision, cheap anyway):
// hw1h[M,64] = fp16( relu(h1)[M,128] @ W1[128,64] )
// ---------------------------------------------------------------------------
template<int BM, int BN, int BK, int TM, int TN, bool RELU_A>
__device__ __forceinline__ void gemm_body_h(const float* __restrict__ A,
                                            const float* __restrict__ B,
                                            __half* __restrict__ C,
                                            int M, int K, int N)
{
    __shared__ float As[BK][BM];   // transposed A tile
    __shared__ float Bs[BK][BN];

    constexpr int THREADS = (BM / TM) * (BN / TN);   // 256
    const int tid = threadIdx.x;
    const int bm  = blockIdx.x * BM;
    const int tx  = tid % (BN / TN);
    const int ty  = tid / (BN / TN);

    unsigned long long acc2[TM][TN / 2];
#pragma unroll
    for (int i = 0; i < TM; i++)
#pragma unroll
        for (int j = 0; j < TN / 2; j++) acc2[i][j] = 0ull;

    for (int k0 = 0; k0 < K; k0 += BK) {
        constexpr int A_ELEMS = BM * BK;
#pragma unroll
        for (int off = 0; off < A_ELEMS; off += THREADS * 4) {
            int idx = off + tid * 4;
            if (idx < A_ELEMS) {
                int ar  = idx / BK;
                int ac  = idx % BK;
                int grow = bm + ar;
                float4 v = make_float4(0.f, 0.f, 0.f, 0.f);
                if (grow < M)
                    v = *(const float4*)(A + (size_t)grow * K + k0 + ac);
                if (RELU_A) {
                    v.x = fmaxf(v.x, 0.f); v.y = fmaxf(v.y, 0.f);
                    v.z = fmaxf(v.z, 0.f); v.w = fmaxf(v.w, 0.f);
                }
                As[ac + 0][ar] = v.x;
                As[ac + 1][ar] = v.y;
                As[ac + 2][ar] = v.z;
                As[ac + 3][ar] = v.w;
            }
        }
        constexpr int B_ELEMS = BK * BN;
#pragma unroll
        for (int off = 0; off < B_ELEMS; off += THREADS * 4) {
            int idx = off + tid * 4;
            if (idx < B_ELEMS) {
                int br = idx / BN;
                int bc = idx % BN;
                *(float4*)&Bs[br][bc] =
                    *(const float4*)(B + (size_t)(k0 + br) * N + bc);
            }
        }
        __syncthreads();

#pragma unroll
        for (int kk = 0; kk < BK; kk++) {
            unsigned long long b2[TN / 2];
#pragma unroll
            for (int j = 0; j < TN / 2; j++)
                b2[j] = *(const unsigned long long*)&Bs[kk][tx * TN + 2 * j];
#pragma unroll
            for (int i = 0; i < TM; i++) {
                float a = As[kk][ty * TM + i];
                unsigned long long a2 = pack2(a, a);
#pragma unroll
                for (int j = 0; j < TN / 2; j++)
                    fma2(acc2[i][j], a2, b2[j]);
            }
        }
        __syncthreads();
    }

#pragma unroll
    for (int i = 0; i < TM; i++) {
        int row = bm + ty * TM + i;
        if (row < M) {
            __half2 h[TN / 2];
#pragma unroll
            for (int j = 0; j < TN / 2; j++) {
                float lo, hi;
                unpack2(acc2[i][j], lo, hi);
                h[j] = __floats2half2_rn(lo, hi);
            }
#pragma unroll
            for (int j = 0; j < TN / 2; j += 2)
                *(uint2*)(C + (size_t)row * N + tx * TN + 2 * j) =
                    *(uint2*)&h[j];
        }
    }
}

__global__ void gemm2_kernel(const float* __restrict__ W1) {
    gemm_body_h<128, 64, 32, 8, 4, true>(g_h1, W1, g_hw1h, N_NODES, H1, H2);
}

// ---------------------------------------------------------------------------
// CSR SPMM layer 1: h1[r] = sum_e w_e * xw0[col_e], F=128 halves.
// One warp per row; lane loads uint2 = 4 halves (cols lane*4..lane*4+3).
// ---------------------------------------------------------------------------
__global__ void spmm1_csr_kernel()
{
    int warp = (int)(((long long)blockIdx.x * blockDim.x + threadIdx.x) >> 5);
    int lane = threadIdx.x & 31;
    if (warp >= N_NODES) return;
    int p  = g_ptr[warp];
    int pe = g_ptr[warp + 1];
    const uint2* __restrict__ h4 = (const uint2*)g_xw0h;   // 4 halves / elem
    float4 acc = make_float4(0.f, 0.f, 0.f, 0.f);

    for (; p + 4 <= pe; p += 4) {
        int2 e0 = g_edge[p],     e1 = g_edge[p + 1];
        int2 e2 = g_edge[p + 2], e3 = g_edge[p + 3];
        uint2 r0 = h4[(size_t)e0.x * 32 + lane];
        uint2 r1 = h4[(size_t)e1.x * 32 + lane];
        uint2 r2 = h4[(size_t)e2.x * 32 + lane];
        uint2 r3 = h4[(size_t)e3.x * 32 + lane];
        float w0 = __int_as_float(e0.y), w1 = __int_as_float(e1.y);
        float w2 = __int_as_float(e2.y), w3 = __int_as_float(e3.y);
        float2 a0 = __half22float2(*(__half2*)&r0.x);
        float2 b0 = __half22float2(*(__half2*)&r0.y);
        float2 a1 = __half22float2(*(__half2*)&r1.x);
        float2 b1 = __half22float2(*(__half2*)&r1.y);
        float2 a2 = __half22float2(*(__half2*)&r2.x);
        float2 b2 = __half22float2(*(__half2*)&r2.y);
        float2 a3 = __half22float2(*(__half2*)&r3.x);
        float2 b3 = __half22float2(*(__half2*)&r3.y);
        acc.x += w0 * a0.x + w1 * a1.x + w2 * a2.x + w3 * a3.x;
        acc.y += w0 * a0.y + w1 * a1.y + w2 * a2.y + w3 * a3.y;
        acc.z += w0 * b0.x + w1 * b1.x + w2 * b2.x + w3 * b3.x;
        acc.w += w0 * b0.y + w1 * b1.y + w2 * b2.y + w3 * b3.y;
    }
    for (; p < pe; p++) {
        int2 e = g_edge[p];
        float w = __int_as_float(e.y);
        uint2 r = h4[(size_t)e.x * 32 + lane];
        float2 a = __half22float2(*(__half2*)&r.x);
        float2 b = __half22float2(*(__half2*)&r.y);
        acc.x += w * a.x; acc.y += w * a.y;
        acc.z += w * b.x; acc.w += w * b.y;
    }
    ((float4*)g_h1)[(size_t)warp * 32 + lane] = acc;
}

// ---------------------------------------------------------------------------
// CSR SPMM layer 2 fused with relu + softmax, F=64 halves.
// ---------------------------------------------------------------------------
__global__ void spmm2_softmax_kernel(float* __restrict__ out)
{
    int warp = (int)(((long long)blockIdx.x * blockDim.x + threadIdx.x) >> 5);
    int lane = threadIdx.x & 31;
    if (warp >= N_NODES) return;
    int p  = g_ptr[warp];
    int pe = g_ptr[warp + 1];
    const unsigned* __restrict__ h2p = (const unsigned*)g_hw1h;  // 2 halves
    float2 acc = make_float2(0.f, 0.f);

    for (; p + 4 <= pe; p += 4) {
        int2 e0 = g_edge[p],     e1 = g_edge[p + 1];
        int2 e2 = g_edge[p + 2], e3 = g_edge[p + 3];
        unsigned r0 = h2p[(size_t)e0.x * 32 + lane];
        unsigned r1 = h2p[(size_t)e1.x * 32 + lane];
        unsigned r2 = h2p[(size_t)e2.x * 32 + lane];
        unsigned r3 = h2p[(size_t)e3.x * 32 + lane];
        float w0 = __int_as_float(e0.y), w1 = __int_as_float(e1.y);
        float w2 = __int_as_float(e2.y), w3 = __int_as_float(e3.y);
        float2 v0 = __half22float2(*(__half2*)&r0);
        float2 v1 = __half22float2(*(__half2*)&r1);
        float2 v2 = __half22float2(*(__half2*)&r2);
        float2 v3 = __half22float2(*(__half2*)&r3);
        acc.x += w0 * v0.x + w1 * v1.x + w2 * v2.x + w3 * v3.x;
        acc.y += w0 * v0.y + w1 * v1.y + w2 * v2.y + w3 * v3.y;
    }
    for (; p < pe; p++) {
        int2 e = g_edge[p];
        float w = __int_as_float(e.y);
        unsigned r = h2p[(size_t)e.x * 32 + lane];
        float2 v = __half22float2(*(__half2*)&r);
        acc.x += w * v.x; acc.y += w * v.y;
    }

    // relu + softmax over the 64 values held by the warp
    float v0 = fmaxf(acc.x, 0.f);
    float v1 = fmaxf(acc.y, 0.f);
    float m = fmaxf(v0, v1);
#pragma unroll
    for (int o = 16; o; o >>= 1) m = fmaxf(m, __shfl_xor_sync(~0u, m, o));
    float e0 = __expf(v0 - m);
    float e1 = __expf(v1 - m);
    float s = e0 + e1;
#pragma unroll
    for (int o = 16; o; o >>= 1) s += __shfl_xor_sync(~0u, s, o);
    float inv = 1.f / s;
    ((float2*)out)[(size_t)warp * 32 + lane] = make_float2(e0 * inv, e1 * inv);
}

// ---------------------------------------------------------------------------
// Launch
// ---------------------------------------------------------------------------
extern "C" void kernel_launch(void* const* d_in, const int* in_sizes, int n_in,
                              void* d_out, int out_size)
{
    // Identify inputs by element count (same logic that passed R3-R6).
    const float* x  = nullptr;
    const float* W0 = nullptr;
    const float* W1 = nullptr;
    const void*  edge_buf[3] = {nullptr, nullptr, nullptr};
    int          edge_sz [3] = {0, 0, 0};
    int n_edge_bufs = 0;

    for (int i = 0; i < n_in; i++) {
        int sz = in_sizes[i];
        if (sz == N_NODES * D_FEAT)       x  = (const float*)d_in[i];
        else if (sz == D_FEAT * H1)       W0 = (const float*)d_in[i];
        else if (sz == H1 * H2)           W1 = (const float*)d_in[i];
        else if (n_edge_bufs < 3) {
            edge_buf[n_edge_bufs] = d_in[i];
            edge_sz [n_edge_bufs] = sz;
            n_edge_bufs++;
        }
    }
    const void*  esrc = edge_buf[0];
    const void*  edst = edge_buf[1];
    const float* ew   = (const float*)edge_buf[2];
    if (edge_sz[0] != edge_sz[1] || edge_sz[1] != edge_sz[2]) {
        int wi = 0;
        if (edge_sz[1] < edge_sz[wi]) wi = 1;
        if (edge_sz[2] < edge_sz[wi]) wi = 2;
        const void* rest[2]; int r = 0;
        for (int i = 0; i < 3; i++) if (i != wi) rest[r++] = edge_buf[i];
        esrc = rest[0]; edst = rest[1];
        ew   = (const float*)edge_buf[wi];
    }
    float* out = (float*)d_out;
    const int E = N_EDGES;

    const int EBLK = (E + 255) / 256;
    const int NBLK = (N_NODES + 255) / 256;
    const int WBLK = (int)(((long long)N_NODES * 32 + 255) / 256);

    // dtype probe + zero + CSR build
    detect_zero_kernel<<<NBLK, 256>>>(esrc);
    hist_kernel<<<EBLK, 256>>>(edst, E);
    scan1_kernel<<<N_SCAN_BLOCKS, SCAN_BLK>>>();
    scan2_kernel<<<1, 128>>>();
    scan3_kernel<<<NBLK, 256>>>(E);
    scatter_kernel<<<EBLK, 256>>>(esrc, edst, ew, E);

    // layer 1: xw0h = fp16(X @ W0) via tensor cores, then h1 = A @ xw0
    gemm1_wmma_kernel<<<(N_NODES + 127) / 128, 256>>>(x, W0);
    spmm1_csr_kernel<<<WBLK, 256>>>();

    // layer 2: hw1h = fp16(relu(h1) @ W1), then out = softmax(relu(A @ hw1))
    gemm2_kernel<<<(N_NODES + 127) / 128, 256>>>(W1);
    spmm2_softmax_kernel<<<WBLK, 256>>>(out);
}